// round 11
// baseline (speedup 1.0000x reference)
#include <cuda_runtime.h>
#include <cuda_bf16.h>
#include <cstdint>

// Problem constants
#define M_ROWS   8192          // B*S
#define HID      2048
#define NQKV     6144
#define NHEADS   16
#define HEADD    128
#define BATCH    4
#define SEQ      2048

// Scratch (device globals: allocation-free rule)
__device__ float g_qkv[M_ROWS * NQKV];     // [8192, 6144] tf32-rounded bits
__device__ float g_attn[M_ROWS * HID];     // [8192, 2048] tf32-rounded bits
__device__ float g_vt[BATCH * NHEADS * HEADD * SEQ];  // V transposed [bh][d][s]
__device__ float g_hst[M_ROWS * HID];      // hs pre-rounded to tf32
__device__ float g_wqt[NQKV * HID];        // w_qkv pre-rounded
__device__ float g_wdt[HID * HID];         // w_dense pre-rounded

// ---------------------------------------------------------------------------
// tf32 helpers (portable PTX, sm_80+; no tcgen05 — harness targets sm_103)
// ---------------------------------------------------------------------------
__device__ __forceinline__ uint32_t cvt_tf32(float f) {
    uint32_t r;
    asm("cvt.rna.tf32.f32 %0, %1;" : "=r"(r) : "f"(f));
    return r;
}

__device__ __forceinline__ void mma_tf32(float& d0, float& d1, float& d2, float& d3,
                                         uint32_t a0, uint32_t a1, uint32_t a2, uint32_t a3,
                                         uint32_t b0, uint32_t b1) {
    asm volatile(
        "mma.sync.aligned.m16n8k8.row.col.f32.tf32.tf32.f32 "
        "{%0,%1,%2,%3}, {%4,%5,%6,%7}, {%8,%9}, {%0,%1,%2,%3};"
        : "+f"(d0), "+f"(d1), "+f"(d2), "+f"(d3)
        : "r"(a0), "r"(a1), "r"(a2), "r"(a3), "r"(b0), "r"(b1));
}

#define CP_ASYNC16(dst, src) \
    asm volatile("cp.async.cg.shared.global [%0], [%1], 16;" \
                 :: "r"(dst), "l"(src))
#define CP_COMMIT()  asm volatile("cp.async.commit_group;" ::: "memory")
#define CP_WAIT(n)   asm volatile("cp.async.wait_group %0;" :: "n"(n) : "memory")

__device__ __forceinline__ uint32_t smem_u32(const void* p) {
    uint32_t a;
    asm("{ .reg .u64 t; cvta.to.shared.u64 t, %1; cvt.u32.u64 %0, t; }"
        : "=r"(a) : "l"(p));
    return a;
}

// ---------------------------------------------------------------------------
// Pre-round fp32 -> tf32 bits (elementwise, float4)
// ---------------------------------------------------------------------------
__global__ void round_tf32_knl(const float4* __restrict__ s,
                               float4* __restrict__ d, int n4)
{
    int i = blockIdx.x * blockDim.x + threadIdx.x;
    if (i < n4) {
        float4 f = s[i];
        uint4 u = make_uint4(cvt_tf32(f.x), cvt_tf32(f.y),
                             cvt_tf32(f.z), cvt_tf32(f.w));
        *(uint4*)(d + i) = u;
    }
}

// ---------------------------------------------------------------------------
// Transpose V section of qkv into g_vt[bh][d][s]  (V already tf32-rounded)
// ---------------------------------------------------------------------------
__global__ void transpose_v_knl(const float* __restrict__ qkv,
                                float* __restrict__ vt)
{
    __shared__ float t[32][33];
    const int bh = blockIdx.z;
    const int b  = bh >> 4;
    const int h  = bh & 15;
    const int s0 = blockIdx.x * 32;
    const int d0 = blockIdx.y * 32;
    const int tx = threadIdx.x, ty = threadIdx.y;   // 32 x 8

    const float* src = qkv + (size_t)(b * SEQ + s0) * NQKV + 4096 + h * HEADD + d0;
#pragma unroll
    for (int j = 0; j < 4; j++)
        t[ty + 8 * j][tx] = src[(size_t)(ty + 8 * j) * NQKV + tx];
    __syncthreads();
    float* dst = vt + ((size_t)bh * HEADD + d0) * SEQ + s0;
#pragma unroll
    for (int j = 0; j < 4; j++)
        dst[(size_t)(ty + 8 * j) * SEQ + tx] = t[tx][ty + 8 * j];
}

// ---------------------------------------------------------------------------
// tf32 tensor-core GEMM v4: C[M,N] = A[M,K] @ Bt[N,K]^T + bias[N]
// A, Bt hold PRE-ROUNDED tf32 bits.
// CTA 128x128, 128 threads = 4 warps (2M x 2N), warp tile 64x64, BK=32.
// 3-stage cp.async, ONE barrier per iter, smem 110.6KB -> 2 CTAs/SM.
// ---------------------------------------------------------------------------
#define G4_PITCH   36
#define G4_STAGE_F (256 * G4_PITCH)            // A(128 rows)+B(128 rows)
#define G4_SMEM    (3 * G4_STAGE_F * 4)        // 110592 bytes

__global__ __launch_bounds__(128, 2)
void gemm_tf32_v4(const float* __restrict__ A,
                  const float* __restrict__ Bt,
                  const float* __restrict__ bias,
                  float* __restrict__ C,
                  int N, int K, int round_out)
{
    extern __shared__ __align__(16) uint32_t smu[];
    const uint32_t smb = smem_u32(smu);

    const int tid  = threadIdx.x;
    const int lane = tid & 31;
    const int wid  = tid >> 5;
    const int gid  = lane >> 2;
    const int tig  = lane & 3;
    const int wm   = (wid & 1) * 64;
    const int wn   = (wid >> 1) * 64;
    const int m0 = blockIdx.y * 128;
    const int n0 = blockIdx.x * 128;

    const int srow = tid >> 3;          // 0..15
    const int sq4  = (tid & 7) * 4;

    float acc[4][8][4];
#pragma unroll
    for (int mt = 0; mt < 4; mt++)
#pragma unroll
        for (int nt = 0; nt < 8; nt++)
#pragma unroll
            for (int c = 0; c < 4; c++) acc[mt][nt][c] = 0.f;

    const int niter = K >> 5;

    // 16 cp.async per thread: rows srow+16j; j<8 -> A rows, j>=8 -> B rows
    auto issue = [&](int kt, int slot) {
        const int k0 = kt << 5;
        const uint32_t sb = smb + (uint32_t)slot * (G4_STAGE_F * 4);
#pragma unroll
        for (int j = 0; j < 8; j++) {
            int row = srow + 16 * j;
            uint32_t dst = sb + (uint32_t)(row * G4_PITCH + sq4) * 4;
            const float* src = A + (size_t)(m0 + row) * K + k0 + sq4;
            CP_ASYNC16(dst, src);
        }
#pragma unroll
        for (int j = 8; j < 16; j++) {
            int row = srow + 16 * j;           // 128..255
            uint32_t dst = sb + (uint32_t)(row * G4_PITCH + sq4) * 4;
            const float* src = Bt + (size_t)(n0 + row - 128) * K + k0 + sq4;
            CP_ASYNC16(dst, src);
        }
    };

    issue(0, 0); CP_COMMIT();
    issue(1, 1); CP_COMMIT();

    for (int kt = 0; kt < niter; kt++) {
        CP_WAIT(1);              // stage kt resident (1 newer group may pend)
        __syncthreads();         // publish; also closes iter kt-1 reads

        const uint32_t* As = smu + (kt % 3) * G4_STAGE_F;
        const uint32_t* Bs = As + 128 * G4_PITCH;

#pragma unroll
        for (int s = 0; s < 4; s++) {
            uint32_t af[4][4], bf[8][2];
#pragma unroll
            for (int mt = 0; mt < 4; mt++) {
                const uint32_t* p = As + (wm + mt * 16 + gid) * G4_PITCH + s * 8 + tig;
                af[mt][0] = p[0];
                af[mt][1] = p[8 * G4_PITCH];
                af[mt][2] = p[4];
                af[mt][3] = p[8 * G4_PITCH + 4];
            }
#pragma unroll
            for (int nt = 0; nt < 8; nt++) {
                const uint32_t* p = Bs + (wn + nt * 8 + gid) * G4_PITCH + s * 8 + tig;
                bf[nt][0] = p[0];
                bf[nt][1] = p[4];
            }
#pragma unroll
            for (int mt = 0; mt < 4; mt++)
#pragma unroll
                for (int nt = 0; nt < 8; nt++)
                    mma_tf32(acc[mt][nt][0], acc[mt][nt][1],
                             acc[mt][nt][2], acc[mt][nt][3],
                             af[mt][0], af[mt][1], af[mt][2], af[mt][3],
                             bf[nt][0], bf[nt][1]);
        }

        // refill slot consumed at iter kt-1 (all warps passed this iter's
        // barrier, which is after their kt-1 compute)
        if (kt + 2 < niter) issue(kt + 2, (kt + 2) % 3);
        CP_COMMIT();             // always commit: uniform group indexing
    }

    // epilogue
#pragma unroll
    for (int mt = 0; mt < 4; mt++) {
        const int r0 = m0 + wm + mt * 16 + gid;
#pragma unroll
        for (int nt = 0; nt < 8; nt++) {
            const int col = n0 + wn + nt * 8 + 2 * tig;
            float2 bb = *(const float2*)(bias + col);
            float v00 = acc[mt][nt][0] + bb.x;
            float v01 = acc[mt][nt][1] + bb.y;
            float v10 = acc[mt][nt][2] + bb.x;
            float v11 = acc[mt][nt][3] + bb.y;
            if (round_out) {
                uint2 o0 = make_uint2(cvt_tf32(v00), cvt_tf32(v01));
                uint2 o1 = make_uint2(cvt_tf32(v10), cvt_tf32(v11));
                *(uint2*)(C + (size_t)r0 * N + col)       = o0;
                *(uint2*)(C + (size_t)(r0 + 8) * N + col) = o1;
            } else {
                *(float2*)(C + (size_t)r0 * N + col)       = make_float2(v00, v01);
                *(float2*)(C + (size_t)(r0 + 8) * N + col) = make_float2(v10, v11);
            }
        }
    }
}

// ---------------------------------------------------------------------------
// Tensor-core flash attention v3 (tf32 mma, causal).
// BQ=64, BK=64, D=128. 128 threads = 4 warps; warp w owns q-rows w*16..+15.
// Q fragments in registers. SINGLE K/Vt buffer (86KB smem -> 2 CTAs/SM;
// the co-resident CTA hides per-iter load latency).
// FIX vs R10: issue_kv stages the FULL tiles — 16 cp.async16 per thread for
// K (64 floats each) and 16 for Vt, with dst step 16B == src step 4 floats.
// ---------------------------------------------------------------------------
#define A3_KP 132                   // K pitch (128 + 4 pad)
#define A3_VP 68                    // Vt pitch (64 + 4 pad)
#define A3_BUF_F (64 * A3_KP + 128 * A3_VP)     // 17152 floats
#define A3_PS_F  (64 * 68)                      // 4352 floats
#define A3_SMEM_F (A3_BUF_F + A3_PS_F)          // 21504 floats
#define A3_SMEM_B (A3_SMEM_F * 4)               // 86016 bytes
#define A3_QP 132

__global__ __launch_bounds__(128, 2)
void attn_mma_v3(const float* __restrict__ qkv,
                 const float* __restrict__ vt,
                 float* __restrict__ out)
{
    const int qt = blockIdx.x;       // 0..31 (q-tiles of 64)
    const int bh = blockIdx.y;       // 0..63
    const int b  = bh >> 4;
    const int h  = bh & 15;
    const int q0 = qt * 64;

    const int tid  = threadIdx.x;
    const int lane = tid & 31;
    const int warp = tid >> 5;
    const int gid  = lane >> 2;
    const int tig  = lane & 3;
    const int wm   = warp * 16;

    extern __shared__ __align__(16) uint32_t asv[];
    const uint32_t smb = smem_u32(asv);
    uint32_t* Ps = asv + A3_BUF_F;

    const float scale = 0.088388347648318447f;
    const float* base  = qkv + (size_t)(b * SEQ) * NQKV + h * HEADD;
    const float* vbase = vt + (size_t)bh * HEADD * SEQ;

    // ---- stage Q (64x128) into buffer area, lift fragments to registers ----
    {
        int r  = tid >> 1;               // 0..63
        int c0 = (tid & 1) * 64;
        const float* qp = base + (size_t)(q0 + r) * NQKV + c0;
        uint32_t* dst = asv + r * A3_QP + c0;
#pragma unroll
        for (int j = 0; j < 16; j++) {
            float4 f = *(const float4*)(qp + j * 4);
            dst[j*4+0] = cvt_tf32(f.x * scale);
            dst[j*4+1] = cvt_tf32(f.y * scale);
            dst[j*4+2] = cvt_tf32(f.z * scale);
            dst[j*4+3] = cvt_tf32(f.w * scale);
        }
    }
    __syncthreads();

    uint32_t qf[16][4];
#pragma unroll
    for (int s = 0; s < 16; s++) {
        const uint32_t* pa = asv + (wm + gid) * A3_QP + s * 8 + tig;
        qf[s][0] = pa[0];
        qf[s][1] = pa[8 * A3_QP];
        qf[s][2] = pa[4];
        qf[s][3] = pa[8 * A3_QP + 4];
    }
    __syncthreads();     // Q staging consumed; buffer reusable for K/Vt

    const int niter = qt + 1;

    // ---- KV issuer: K tile [64][128] + Vt tile [128][64] ----
    // K: thread -> row tid>>1, half (tid&1)*64; 16 quads (64 floats).
    // Vt: thread -> d-row tid; 16 quads (64 floats).
    auto issue_kv = [&](int kt) {
        const int k0 = kt * 64;
        {
            int r  = tid >> 1;
            int c0 = (tid & 1) * 64;
            const float* src0 = base + 2048 + (size_t)(k0 + r) * NQKV + c0;
            uint32_t d0 = smb + (uint32_t)(r * A3_KP + c0) * 4;
#pragma unroll
            for (int j = 0; j < 16; j++)
                CP_ASYNC16(d0 + j * 16, src0 + j * 4);
        }
        {
            const float* src0 = vbase + (size_t)tid * SEQ + k0;
            uint32_t d0 = smb + (uint32_t)(64 * A3_KP + tid * A3_VP) * 4;
#pragma unroll
            for (int j = 0; j < 16; j++)
                CP_ASYNC16(d0 + j * 16, src0 + j * 4);
        }
    };

    issue_kv(0); CP_COMMIT();

    float O[16][4];
#pragma unroll
    for (int nt = 0; nt < 16; nt++)
#pragma unroll
        for (int c = 0; c < 4; c++) O[nt][c] = 0.f;
    float m0r = -1e30f, m1r = -1e30f;
    float l0r = 0.f,    l1r = 0.f;

    const int rA = q0 + wm + gid;
    const int rB = rA + 8;

    const uint32_t* Ks = asv;
    const uint32_t* Vs = asv + 64 * A3_KP;

    for (int kt = 0; kt < niter; kt++) {
        const int k0 = kt * 64;
        CP_WAIT(0);
        __syncthreads();

        // ---- S = Q K^T ----
        float acc[8][4];
#pragma unroll
        for (int nt = 0; nt < 8; nt++)
#pragma unroll
            for (int c = 0; c < 4; c++) acc[nt][c] = 0.f;

#pragma unroll
        for (int s = 0; s < 16; s++) {
#pragma unroll
            for (int nt = 0; nt < 8; nt++) {
                const uint32_t* pb = Ks + (nt * 8 + gid) * A3_KP + s * 8 + tig;
                mma_tf32(acc[nt][0], acc[nt][1], acc[nt][2], acc[nt][3],
                         qf[s][0], qf[s][1], qf[s][2], qf[s][3],
                         pb[0], pb[4]);
            }
        }

        // ---- causal mask (diagonal tile only) ----
        if (kt == niter - 1) {
#pragma unroll
            for (int nt = 0; nt < 8; nt++) {
                int c0c = k0 + nt * 8 + 2 * tig;
                if (c0c > rA)     acc[nt][0] = -1e30f;
                if (c0c + 1 > rA) acc[nt][1] = -1e30f;
                if (c0c > rB)     acc[nt][2] = -1e30f;
                if (c0c + 1 > rB) acc[nt][3] = -1e30f;
            }
        }

        // ---- online softmax (4-lane groups share a row) ----
        float mx0 = -1e30f, mx1 = -1e30f;
#pragma unroll
        for (int nt = 0; nt < 8; nt++) {
            mx0 = fmaxf(mx0, fmaxf(acc[nt][0], acc[nt][1]));
            mx1 = fmaxf(mx1, fmaxf(acc[nt][2], acc[nt][3]));
        }
        mx0 = fmaxf(mx0, __shfl_xor_sync(0xffffffffu, mx0, 1));
        mx0 = fmaxf(mx0, __shfl_xor_sync(0xffffffffu, mx0, 2));
        mx1 = fmaxf(mx1, __shfl_xor_sync(0xffffffffu, mx1, 1));
        mx1 = fmaxf(mx1, __shfl_xor_sync(0xffffffffu, mx1, 2));

        float mn0 = fmaxf(m0r, mx0);
        float mn1 = fmaxf(m1r, mx1);
        float al0 = __expf(m0r - mn0);
        float al1 = __expf(m1r - mn1);

        float s0 = 0.f, s1 = 0.f;
        uint32_t* prowA = Ps + (wm + gid) * 68 + 2 * tig;
        uint32_t* prowB = prowA + 8 * 68;
#pragma unroll
        for (int nt = 0; nt < 8; nt++) {
            float p00 = __expf(acc[nt][0] - mn0);
            float p01 = __expf(acc[nt][1] - mn0);
            float p10 = __expf(acc[nt][2] - mn1);
            float p11 = __expf(acc[nt][3] - mn1);
            s0 += p00 + p01;
            s1 += p10 + p11;
            *(uint2*)(prowA + nt * 8) = make_uint2(cvt_tf32(p00), cvt_tf32(p01));
            *(uint2*)(prowB + nt * 8) = make_uint2(cvt_tf32(p10), cvt_tf32(p11));
        }
        s0 += __shfl_xor_sync(0xffffffffu, s0, 1);
        s0 += __shfl_xor_sync(0xffffffffu, s0, 2);
        s1 += __shfl_xor_sync(0xffffffffu, s1, 1);
        s1 += __shfl_xor_sync(0xffffffffu, s1, 2);

        l0r = l0r * al0 + s0;  m0r = mn0;
        l1r = l1r * al1 + s1;  m1r = mn1;

#pragma unroll
        for (int nt = 0; nt < 16; nt++) {
            O[nt][0] *= al0;  O[nt][1] *= al0;
            O[nt][2] *= al1;  O[nt][3] *= al1;
        }
        __syncwarp();   // Ps rows are warp-private

        // ---- O += P V ----
#pragma unroll
        for (int s = 0; s < 8; s++) {
            const uint32_t* pa = Ps + (wm + gid) * 68 + s * 8 + tig;
            uint32_t a0 = pa[0];
            uint32_t a1 = pa[8 * 68];
            uint32_t a2 = pa[4];
            uint32_t a3 = pa[8 * 68 + 4];
#pragma unroll
            for (int nt = 0; nt < 16; nt++) {
                const uint32_t* pb = Vs + (nt * 8 + gid) * A3_VP + s * 8 + tig;
                mma_tf32(O[nt][0], O[nt][1], O[nt][2], O[nt][3],
                         a0, a1, a2, a3, pb[0], pb[4]);
            }
        }

        __syncthreads();   // all warps done reading the buffer
        if (kt + 1 < niter) issue_kv(kt + 1);
        CP_COMMIT();       // always commit (uniform group indexing)
    }

    // ---- epilogue: normalize, round to tf32 (dense GEMM consumes raw) ----
    const float inv0 = 1.0f / l0r;
    const float inv1 = 1.0f / l1r;
    uint32_t* outA = (uint32_t*)(out + (size_t)(b * SEQ + rA) * HID + h * HEADD + 2 * tig);
    uint32_t* outB = (uint32_t*)(out + (size_t)(b * SEQ + rB) * HID + h * HEADD + 2 * tig);
#pragma unroll
    for (int nt = 0; nt < 16; nt++) {
        uint2 oa, ob;
        oa.x = cvt_tf32(O[nt][0] * inv0);  oa.y = cvt_tf32(O[nt][1] * inv0);
        ob.x = cvt_tf32(O[nt][2] * inv1);  ob.y = cvt_tf32(O[nt][3] * inv1);
        *(uint2*)(outA + nt * 8) = oa;
        *(uint2*)(outB + nt * 8) = ob;
    }
}

// ---------------------------------------------------------------------------
// Launch: pre-round -> QKV GEMM (tf32 out) -> V transpose -> attention -> dense
// ---------------------------------------------------------------------------
extern "C" void kernel_launch(void* const* d_in, const int* in_sizes, int n_in,
                              void* d_out, int out_size)
{
    (void)in_sizes; (void)n_in; (void)out_size;
    const float* hs   = (const float*)d_in[0];
    const float* wqkv = (const float*)d_in[1];
    const float* bqkv = (const float*)d_in[2];
    const float* wd   = (const float*)d_in[3];
    const float* bd   = (const float*)d_in[4];
    float* out = (float*)d_out;

    float *qkv, *attn, *vt, *hst, *wqt, *wdt;
    cudaGetSymbolAddress((void**)&qkv,  g_qkv);
    cudaGetSymbolAddress((void**)&attn, g_attn);
    cudaGetSymbolAddress((void**)&vt,   g_vt);
    cudaGetSymbolAddress((void**)&hst,  g_hst);
    cudaGetSymbolAddress((void**)&wqt,  g_wqt);
    cudaGetSymbolAddress((void**)&wdt,  g_wdt);

    cudaFuncSetAttribute(gemm_tf32_v4,
                         cudaFuncAttributeMaxDynamicSharedMemorySize, G4_SMEM);
    cudaFuncSetAttribute(attn_mma_v3,
                         cudaFuncAttributeMaxDynamicSharedMemorySize, A3_SMEM_B);

    // 0) pre-round inputs to tf32 bits
    {
        int n4;
        n4 = (M_ROWS * HID) / 4;
        round_tf32_knl<<<(n4 + 255) / 256, 256>>>((const float4*)hs,   (float4*)hst, n4);
        n4 = (NQKV * HID) / 4;
        round_tf32_knl<<<(n4 + 255) / 256, 256>>>((const float4*)wqkv, (float4*)wqt, n4);
        n4 = (HID * HID) / 4;
        round_tf32_knl<<<(n4 + 255) / 256, 256>>>((const float4*)wd,   (float4*)wdt, n4);
    }
    // 1) qkv = hs @ w_qkv^T + b_qkv      [8192, 6144], tf32-rounded output
    {
        dim3 grid(NQKV / 128, M_ROWS / 128);
        gemm_tf32_v4<<<grid, 128, G4_SMEM>>>(hst, wqt, bqkv, qkv, NQKV, HID, 1);
    }
    // 1b) transpose V into g_vt[bh][d][s]
    {
        dim3 grid(SEQ / 32, HEADD / 32, BATCH * NHEADS);
        transpose_v_knl<<<grid, dim3(32, 8)>>>(qkv, vt);
    }
    // 2) causal flash attention          [8192, 2048], tf32-rounded output
    {
        dim3 grid(SEQ / 64, BATCH * NHEADS);
        attn_mma_v3<<<grid, 128, A3_SMEM_B>>>(qkv, vt, attn);
    }
    // 3) out = attn @ w_dense^T + b_dense [8192, 2048], fp32 output
    {
        dim3 grid(HID / 128, M_ROWS / 128);
        gemm_tf32_v4<<<grid, 128, G4_SMEM>>>(attn, wdt, bd, out, HID, HID, 0);
    }
}

// round 13
// speedup vs baseline: 1.0730x; 1.0730x over previous
#include <cuda_runtime.h>
#include <cuda_bf16.h>
#include <cstdint>

// Problem constants
#define M_ROWS   8192          // B*S
#define HID      2048
#define NQKV     6144
#define NHEADS   16
#define HEADD    128
#define BATCH    4
#define SEQ      2048

// Scratch (device globals: allocation-free rule)
__device__ float g_qkv[M_ROWS * NQKV];     // [8192, 6144] tf32-rounded bits
__device__ float g_attn[M_ROWS * HID];     // [8192, 2048] tf32-rounded bits
__device__ float g_vt[BATCH * NHEADS * HEADD * SEQ];  // V transposed [bh][d][s]
__device__ float g_hst[M_ROWS * HID];      // hs pre-rounded to tf32
__device__ float g_wqt[NQKV * HID];        // w_qkv pre-rounded
__device__ float g_wdt[HID * HID];         // w_dense pre-rounded

// ---------------------------------------------------------------------------
// tf32 helpers (portable PTX, sm_80+; no tcgen05 — harness targets sm_103)
// ---------------------------------------------------------------------------
__device__ __forceinline__ uint32_t cvt_tf32(float f) {
    uint32_t r;
    asm("cvt.rna.tf32.f32 %0, %1;" : "=r"(r) : "f"(f));
    return r;
}

__device__ __forceinline__ void mma_tf32(float& d0, float& d1, float& d2, float& d3,
                                         uint32_t a0, uint32_t a1, uint32_t a2, uint32_t a3,
                                         uint32_t b0, uint32_t b1) {
    asm volatile(
        "mma.sync.aligned.m16n8k8.row.col.f32.tf32.tf32.f32 "
        "{%0,%1,%2,%3}, {%4,%5,%6,%7}, {%8,%9}, {%0,%1,%2,%3};"
        : "+f"(d0), "+f"(d1), "+f"(d2), "+f"(d3)
        : "r"(a0), "r"(a1), "r"(a2), "r"(a3), "r"(b0), "r"(b1));
}

#define CP_ASYNC16(dst, src) \
    asm volatile("cp.async.cg.shared.global [%0], [%1], 16;" \
                 :: "r"(dst), "l"(src))
#define CP_COMMIT()  asm volatile("cp.async.commit_group;" ::: "memory")
#define CP_WAIT(n)   asm volatile("cp.async.wait_group %0;" :: "n"(n) : "memory")

__device__ __forceinline__ uint32_t smem_u32(const void* p) {
    uint32_t a;
    asm("{ .reg .u64 t; cvta.to.shared.u64 t, %1; cvt.u32.u64 %0, t; }"
        : "=r"(a) : "l"(p));
    return a;
}

// ---------------------------------------------------------------------------
// Pre-round fp32 -> tf32 bits (elementwise, float4)
// ---------------------------------------------------------------------------
__global__ void round_tf32_knl(const float4* __restrict__ s,
                               float4* __restrict__ d, int n4)
{
    int i = blockIdx.x * blockDim.x + threadIdx.x;
    if (i < n4) {
        float4 f = s[i];
        uint4 u = make_uint4(cvt_tf32(f.x), cvt_tf32(f.y),
                             cvt_tf32(f.z), cvt_tf32(f.w));
        *(uint4*)(d + i) = u;
    }
}

// ---------------------------------------------------------------------------
// Transpose V section of qkv into g_vt[bh][d][s]  (V already tf32-rounded)
// ---------------------------------------------------------------------------
__global__ void transpose_v_knl(const float* __restrict__ qkv,
                                float* __restrict__ vt)
{
    __shared__ float t[32][33];
    const int bh = blockIdx.z;
    const int b  = bh >> 4;
    const int h  = bh & 15;
    const int s0 = blockIdx.x * 32;
    const int d0 = blockIdx.y * 32;
    const int tx = threadIdx.x, ty = threadIdx.y;   // 32 x 8

    const float* src = qkv + (size_t)(b * SEQ + s0) * NQKV + 4096 + h * HEADD + d0;
#pragma unroll
    for (int j = 0; j < 4; j++)
        t[ty + 8 * j][tx] = src[(size_t)(ty + 8 * j) * NQKV + tx];
    __syncthreads();
    float* dst = vt + ((size_t)bh * HEADD + d0) * SEQ + s0;
#pragma unroll
    for (int j = 0; j < 4; j++)
        dst[(size_t)(ty + 8 * j) * SEQ + tx] = t[tx][ty + 8 * j];
}

// ---------------------------------------------------------------------------
// tf32 tensor-core GEMM v4: C[M,N] = A[M,K] @ Bt[N,K]^T + bias[N]
// A, Bt hold PRE-ROUNDED tf32 bits.
// CTA 128x128, 128 threads = 4 warps (2M x 2N), warp tile 64x64, BK=32.
// 3-stage cp.async, ONE barrier per iter, smem 110.6KB -> 2 CTAs/SM.
// (unchanged from R11 — QKV phase verified at 1.090ms, tensor 62.1%)
// ---------------------------------------------------------------------------
#define G4_PITCH   36
#define G4_STAGE_F (256 * G4_PITCH)            // A(128 rows)+B(128 rows)
#define G4_SMEM    (3 * G4_STAGE_F * 4)        // 110592 bytes

__global__ __launch_bounds__(128, 2)
void gemm_tf32_v4(const float* __restrict__ A,
                  const float* __restrict__ Bt,
                  const float* __restrict__ bias,
                  float* __restrict__ C,
                  int N, int K, int round_out)
{
    extern __shared__ __align__(16) uint32_t smu[];
    const uint32_t smb = smem_u32(smu);

    const int tid  = threadIdx.x;
    const int lane = tid & 31;
    const int wid  = tid >> 5;
    const int gid  = lane >> 2;
    const int tig  = lane & 3;
    const int wm   = (wid & 1) * 64;
    const int wn   = (wid >> 1) * 64;
    const int m0 = blockIdx.y * 128;
    const int n0 = blockIdx.x * 128;

    const int srow = tid >> 3;          // 0..15
    const int sq4  = (tid & 7) * 4;

    float acc[4][8][4];
#pragma unroll
    for (int mt = 0; mt < 4; mt++)
#pragma unroll
        for (int nt = 0; nt < 8; nt++)
#pragma unroll
            for (int c = 0; c < 4; c++) acc[mt][nt][c] = 0.f;

    const int niter = K >> 5;

    auto issue = [&](int kt, int slot) {
        const int k0 = kt << 5;
        const uint32_t sb = smb + (uint32_t)slot * (G4_STAGE_F * 4);
#pragma unroll
        for (int j = 0; j < 8; j++) {
            int row = srow + 16 * j;
            uint32_t dst = sb + (uint32_t)(row * G4_PITCH + sq4) * 4;
            const float* src = A + (size_t)(m0 + row) * K + k0 + sq4;
            CP_ASYNC16(dst, src);
        }
#pragma unroll
        for (int j = 8; j < 16; j++) {
            int row = srow + 16 * j;           // 128..255
            uint32_t dst = sb + (uint32_t)(row * G4_PITCH + sq4) * 4;
            const float* src = Bt + (size_t)(n0 + row - 128) * K + k0 + sq4;
            CP_ASYNC16(dst, src);
        }
    };

    issue(0, 0); CP_COMMIT();
    issue(1, 1); CP_COMMIT();

    for (int kt = 0; kt < niter; kt++) {
        CP_WAIT(1);
        __syncthreads();

        const uint32_t* As = smu + (kt % 3) * G4_STAGE_F;
        const uint32_t* Bs = As + 128 * G4_PITCH;

#pragma unroll
        for (int s = 0; s < 4; s++) {
            uint32_t af[4][4], bf[8][2];
#pragma unroll
            for (int mt = 0; mt < 4; mt++) {
                const uint32_t* p = As + (wm + mt * 16 + gid) * G4_PITCH + s * 8 + tig;
                af[mt][0] = p[0];
                af[mt][1] = p[8 * G4_PITCH];
                af[mt][2] = p[4];
                af[mt][3] = p[8 * G4_PITCH + 4];
            }
#pragma unroll
            for (int nt = 0; nt < 8; nt++) {
                const uint32_t* p = Bs + (wn + nt * 8 + gid) * G4_PITCH + s * 8 + tig;
                bf[nt][0] = p[0];
                bf[nt][1] = p[4];
            }
#pragma unroll
            for (int mt = 0; mt < 4; mt++)
#pragma unroll
                for (int nt = 0; nt < 8; nt++)
                    mma_tf32(acc[mt][nt][0], acc[mt][nt][1],
                             acc[mt][nt][2], acc[mt][nt][3],
                             af[mt][0], af[mt][1], af[mt][2], af[mt][3],
                             bf[nt][0], bf[nt][1]);
        }

        if (kt + 2 < niter) issue(kt + 2, (kt + 2) % 3);
        CP_COMMIT();
    }

    // epilogue
#pragma unroll
    for (int mt = 0; mt < 4; mt++) {
        const int r0 = m0 + wm + mt * 16 + gid;
#pragma unroll
        for (int nt = 0; nt < 8; nt++) {
            const int col = n0 + wn + nt * 8 + 2 * tig;
            float2 bb = *(const float2*)(bias + col);
            float v00 = acc[mt][nt][0] + bb.x;
            float v01 = acc[mt][nt][1] + bb.y;
            float v10 = acc[mt][nt][2] + bb.x;
            float v11 = acc[mt][nt][3] + bb.y;
            if (round_out) {
                uint2 o0 = make_uint2(cvt_tf32(v00), cvt_tf32(v01));
                uint2 o1 = make_uint2(cvt_tf32(v10), cvt_tf32(v11));
                *(uint2*)(C + (size_t)r0 * N + col)       = o0;
                *(uint2*)(C + (size_t)(r0 + 8) * N + col) = o1;
            } else {
                *(float2*)(C + (size_t)r0 * N + col)       = make_float2(v00, v01);
                *(float2*)(C + (size_t)(r0 + 8) * N + col) = make_float2(v10, v11);
            }
        }
    }
}

// ---------------------------------------------------------------------------
// Tensor-core flash attention v2 (tf32 mma, causal) — R9 passing version,
// plus longest-first qt remap (qt = gridDim.x - 1 - blockIdx.x).
// BQ=128, BK=64, D=128. 256 threads = 8 warps; warp w owns q-rows w*16..+15.
// Q fragments in registers; K/Vt double-buffered via cp.async.
// ---------------------------------------------------------------------------
#define AV_KP 132
#define AV_VP 68
#define AV_BUF_F (64 * AV_KP + 128 * AV_VP)     // 17152 floats per stage
#define AV_PS_F  (128 * 68)                     // 8704 floats
#define AV_SMEM_F (2 * AV_BUF_F + AV_PS_F)      // 43008 floats
#define AV_SMEM_B (AV_SMEM_F * 4)               // 172032 bytes
#define AV_QP 132

__global__ __launch_bounds__(256, 1)
void attn_mma_v2(const float* __restrict__ qkv,
                 const float* __restrict__ vt,
                 float* __restrict__ out)
{
    const int qt = (int)gridDim.x - 1 - (int)blockIdx.x;  // longest-first
    const int bh = blockIdx.y;
    const int b  = bh >> 4;
    const int h  = bh & 15;
    const int q0 = qt * 128;

    const int tid  = threadIdx.x;
    const int lane = tid & 31;
    const int warp = tid >> 5;
    const int gid  = lane >> 2;
    const int tig  = lane & 3;
    const int wm   = warp * 16;

    extern __shared__ __align__(16) uint32_t asv[];
    const uint32_t smb = smem_u32(asv);
    uint32_t* Ps = asv + 2 * AV_BUF_F;

    const float scale = 0.088388347648318447f;
    const float* base  = qkv + (size_t)(b * SEQ) * NQKV + h * HEADD;
    const float* vbase = vt + (size_t)bh * HEADD * SEQ;

    // ---- stage Q into (temporary) smem, lift fragments to registers ----
    {
        int r  = tid >> 1;
        int c0 = (tid & 1) * 64;
        const float* qp = base + (size_t)(q0 + r) * NQKV + c0;
        uint32_t* dst = asv + r * AV_QP + c0;
#pragma unroll
        for (int j = 0; j < 16; j++) {
            float4 f = *(const float4*)(qp + j * 4);
            dst[j*4+0] = cvt_tf32(f.x * scale);
            dst[j*4+1] = cvt_tf32(f.y * scale);
            dst[j*4+2] = cvt_tf32(f.z * scale);
            dst[j*4+3] = cvt_tf32(f.w * scale);
        }
    }
    __syncthreads();

    uint32_t qf[16][4];
#pragma unroll
    for (int s = 0; s < 16; s++) {
        const uint32_t* pa = asv + (wm + gid) * AV_QP + s * 8 + tig;
        qf[s][0] = pa[0];
        qf[s][1] = pa[8 * AV_QP];
        qf[s][2] = pa[4];
        qf[s][3] = pa[8 * AV_QP + 4];
    }
    __syncthreads();     // Q staging consumed; buffers reusable

    const int niter = qt * 2 + 2;

    // ---- KV stage issuer: K tile [64][128], Vt tile [128][64] ----
    auto issue_kv = [&](int kt, int slot) {
        const int k0 = kt * 64;
        const uint32_t sb = smb + (uint32_t)slot * (AV_BUF_F * 4);
        {
            int r = tid >> 2;
            const float* src0 = base + 2048 + (size_t)(k0 + r) * NQKV;
            uint32_t d0 = sb + (uint32_t)(r * AV_KP) * 4;
#pragma unroll
            for (int j = 0; j < 8; j++) {
                int col = ((tid & 3) * 8 + j) * 4;
                CP_ASYNC16(d0 + col * 4, src0 + col);
            }
        }
        {
            int d = tid >> 1;
            const float* src0 = vbase + (size_t)d * SEQ + k0;
            uint32_t d0 = sb + (uint32_t)(64 * AV_KP + d * AV_VP) * 4;
#pragma unroll
            for (int j = 0; j < 8; j++) {
                int col = ((tid & 1) * 8 + j) * 4;
                CP_ASYNC16(d0 + col * 4, src0 + col);
            }
        }
    };

    issue_kv(0, 0); CP_COMMIT();
    if (niter > 1) issue_kv(1, 1);
    CP_COMMIT();

    float O[16][4];
#pragma unroll
    for (int nt = 0; nt < 16; nt++)
#pragma unroll
        for (int c = 0; c < 4; c++) O[nt][c] = 0.f;
    float m0r = -1e30f, m1r = -1e30f;
    float l0r = 0.f,    l1r = 0.f;

    const int rA = q0 + wm + gid;
    const int rB = rA + 8;

    for (int kt = 0; kt < niter; kt++) {
        const int k0 = kt * 64;
        CP_WAIT(1);
        __syncthreads();

        const uint32_t* Ks = asv + (kt & 1) * AV_BUF_F;
        const uint32_t* Vs = Ks + 64 * AV_KP;

        // ---- S = Q K^T ----
        float acc[8][4];
#pragma unroll
        for (int nt = 0; nt < 8; nt++)
#pragma unroll
            for (int c = 0; c < 4; c++) acc[nt][c] = 0.f;

#pragma unroll
        for (int s = 0; s < 16; s++) {
#pragma unroll
            for (int nt = 0; nt < 8; nt++) {
                const uint32_t* pb = Ks + (nt * 8 + gid) * AV_KP + s * 8 + tig;
                mma_tf32(acc[nt][0], acc[nt][1], acc[nt][2], acc[nt][3],
                         qf[s][0], qf[s][1], qf[s][2], qf[s][3],
                         pb[0], pb[4]);
            }
        }

        // ---- causal mask ----
        if (kt >= niter - 2) {
#pragma unroll
            for (int nt = 0; nt < 8; nt++) {
                int c0c = k0 + nt * 8 + 2 * tig;
                if (c0c > rA)     acc[nt][0] = -1e30f;
                if (c0c + 1 > rA) acc[nt][1] = -1e30f;
                if (c0c > rB)     acc[nt][2] = -1e30f;
                if (c0c + 1 > rB) acc[nt][3] = -1e30f;
            }
        }

        // ---- online softmax (4-lane groups share a row) ----
        float mx0 = -1e30f, mx1 = -1e30f;
#pragma unroll
        for (int nt = 0; nt < 8; nt++) {
            mx0 = fmaxf(mx0, fmaxf(acc[nt][0], acc[nt][1]));
            mx1 = fmaxf(mx1, fmaxf(acc[nt][2], acc[nt][3]));
        }
        mx0 = fmaxf(mx0, __shfl_xor_sync(0xffffffffu, mx0, 1));
        mx0 = fmaxf(mx0, __shfl_xor_sync(0xffffffffu, mx0, 2));
        mx1 = fmaxf(mx1, __shfl_xor_sync(0xffffffffu, mx1, 1));
        mx1 = fmaxf(mx1, __shfl_xor_sync(0xffffffffu, mx1, 2));

        float mn0 = fmaxf(m0r, mx0);
        float mn1 = fmaxf(m1r, mx1);
        float al0 = __expf(m0r - mn0);
        float al1 = __expf(m1r - mn1);

        float s0 = 0.f, s1 = 0.f;
        uint32_t* prowA = Ps + (wm + gid) * 68 + 2 * tig;
        uint32_t* prowB = prowA + 8 * 68;
#pragma unroll
        for (int nt = 0; nt < 8; nt++) {
            float p00 = __expf(acc[nt][0] - mn0);
            float p01 = __expf(acc[nt][1] - mn0);
            float p10 = __expf(acc[nt][2] - mn1);
            float p11 = __expf(acc[nt][3] - mn1);
            s0 += p00 + p01;
            s1 += p10 + p11;
            *(uint2*)(prowA + nt * 8) = make_uint2(cvt_tf32(p00), cvt_tf32(p01));
            *(uint2*)(prowB + nt * 8) = make_uint2(cvt_tf32(p10), cvt_tf32(p11));
        }
        s0 += __shfl_xor_sync(0xffffffffu, s0, 1);
        s0 += __shfl_xor_sync(0xffffffffu, s0, 2);
        s1 += __shfl_xor_sync(0xffffffffu, s1, 1);
        s1 += __shfl_xor_sync(0xffffffffu, s1, 2);

        l0r = l0r * al0 + s0;  m0r = mn0;
        l1r = l1r * al1 + s1;  m1r = mn1;

#pragma unroll
        for (int nt = 0; nt < 16; nt++) {
            O[nt][0] *= al0;  O[nt][1] *= al0;
            O[nt][2] *= al1;  O[nt][3] *= al1;
        }
        __syncwarp();   // Ps rows are warp-private

        // ---- O += P V ----
#pragma unroll
        for (int s = 0; s < 8; s++) {
            const uint32_t* pa = Ps + (wm + gid) * 68 + s * 8 + tig;
            uint32_t a0 = pa[0];
            uint32_t a1 = pa[8 * 68];
            uint32_t a2 = pa[4];
            uint32_t a3 = pa[8 * 68 + 4];
#pragma unroll
            for (int nt = 0; nt < 16; nt++) {
                const uint32_t* pb = Vs + (nt * 8 + gid) * AV_VP + s * 8 + tig;
                mma_tf32(O[nt][0], O[nt][1], O[nt][2], O[nt][3],
                         a0, a1, a2, a3, pb[0], pb[4]);
            }
        }

        __syncthreads();   // all warps done reading buffer kt&1
        if (kt + 2 < niter) issue_kv(kt + 2, kt & 1);
        CP_COMMIT();
    }

    // ---- epilogue: normalize, round to tf32 (dense GEMM consumes raw) ----
    const float inv0 = 1.0f / l0r;
    const float inv1 = 1.0f / l1r;
    uint32_t* outA = (uint32_t*)(out + (size_t)(b * SEQ + rA) * HID + h * HEADD + 2 * tig);
    uint32_t* outB = (uint32_t*)(out + (size_t)(b * SEQ + rB) * HID + h * HEADD + 2 * tig);
#pragma unroll
    for (int nt = 0; nt < 16; nt++) {
        uint2 oa, ob;
        oa.x = cvt_tf32(O[nt][0] * inv0);  oa.y = cvt_tf32(O[nt][1] * inv0);
        ob.x = cvt_tf32(O[nt][2] * inv1);  ob.y = cvt_tf32(O[nt][3] * inv1);
        *(uint2*)(outA + nt * 8) = oa;
        *(uint2*)(outB + nt * 8) = ob;
    }
}

// ---------------------------------------------------------------------------
// Launch: pre-round -> QKV GEMM (tf32 out) -> V transpose -> attention -> dense
// ---------------------------------------------------------------------------
extern "C" void kernel_launch(void* const* d_in, const int* in_sizes, int n_in,
                              void* d_out, int out_size)
{
    (void)in_sizes; (void)n_in; (void)out_size;
    const float* hs   = (const float*)d_in[0];
    const float* wqkv = (const float*)d_in[1];
    const float* bqkv = (const float*)d_in[2];
    const float* wd   = (const float*)d_in[3];
    const float* bd   = (const float*)d_in[4];
    float* out = (float*)d_out;

    float *qkv, *attn, *vt, *hst, *wqt, *wdt;
    cudaGetSymbolAddress((void**)&qkv,  g_qkv);
    cudaGetSymbolAddress((void**)&attn, g_attn);
    cudaGetSymbolAddress((void**)&vt,   g_vt);
    cudaGetSymbolAddress((void**)&hst,  g_hst);
    cudaGetSymbolAddress((void**)&wqt,  g_wqt);
    cudaGetSymbolAddress((void**)&wdt,  g_wdt);

    cudaFuncSetAttribute(gemm_tf32_v4,
                         cudaFuncAttributeMaxDynamicSharedMemorySize, G4_SMEM);
    cudaFuncSetAttribute(attn_mma_v2,
                         cudaFuncAttributeMaxDynamicSharedMemorySize, AV_SMEM_B);

    // 0) pre-round inputs to tf32 bits
    {
        int n4;
        n4 = (M_ROWS * HID) / 4;
        round_tf32_knl<<<(n4 + 255) / 256, 256>>>((const float4*)hs,   (float4*)hst, n4);
        n4 = (NQKV * HID) / 4;
        round_tf32_knl<<<(n4 + 255) / 256, 256>>>((const float4*)wqkv, (float4*)wqt, n4);
        n4 = (HID * HID) / 4;
        round_tf32_knl<<<(n4 + 255) / 256, 256>>>((const float4*)wd,   (float4*)wdt, n4);
    }
    // 1) qkv = hs @ w_qkv^T + b_qkv      [8192, 6144], tf32-rounded output
    {
        dim3 grid(NQKV / 128, M_ROWS / 128);
        gemm_tf32_v4<<<grid, 128, G4_SMEM>>>(hst, wqt, bqkv, qkv, NQKV, HID, 1);
    }
    // 1b) transpose V into g_vt[bh][d][s]
    {
        dim3 grid(SEQ / 32, HEADD / 32, BATCH * NHEADS);
        transpose_v_knl<<<grid, dim3(32, 8)>>>(qkv, vt);
    }
    // 2) causal flash attention          [8192, 2048], tf32-rounded output
    {
        dim3 grid(SEQ / 128, BATCH * NHEADS);
        attn_mma_v2<<<grid, 256, AV_SMEM_B>>>(qkv, vt, attn);
    }
    // 3) out = attn @ w_dense^T + b_dense [8192, 2048], fp32 output
    {
        dim3 grid(HID / 128, M_ROWS / 128);
        gemm_tf32_v4<<<grid, 128, G4_SMEM>>>(attn, wdt, bd, out, HID, HID, 0);
    }
}